// round 14
// baseline (speedup 1.0000x reference)
#include <cuda_runtime.h>
#include <cstddef>

namespace {
constexpr int Bsz = 512, Tsz = 1024, Hs = 64;
}

using ull = unsigned long long;

__device__ __forceinline__ void unpack2(ull v, float& lo, float& hi) {
    asm("mov.b64 {%0,%1},%2;" : "=f"(lo), "=f"(hi) : "l"(v));
}
__device__ __forceinline__ ull ffma2(ull a, ull b, ull c) {
    ull d;
    asm("fma.rn.f32x2 %0,%1,%2,%3;" : "=l"(d) : "l"(a), "l"(b), "l"(c));
    return d;
}
__device__ __forceinline__ float fast_ex2(float x) {
    float r; asm("ex2.approx.f32 %0,%1;" : "=f"(r) : "f"(x)); return r;
}
__device__ __forceinline__ float fast_rcp(float x) {
    float r; asm("rcp.approx.f32 %0,%1;" : "=f"(r) : "f"(x)); return r;
}
__device__ __forceinline__ float fsigmoid(float x) {
    return fast_rcp(1.0f + fast_ex2(-1.44269504f * x));
}
__device__ __forceinline__ float ftanh(float x) {
    float ax = fabsf(x);
    float t  = fast_ex2(-2.88539008f * ax);          // exp(-2|x|)
    float y  = (1.0f - t) * fast_rcp(1.0f + t);
    return copysignf(y, x);
}

#define BAR_SYNC(id, cnt)   asm volatile("bar.sync %0, %1;"   :: "r"(id), "r"(cnt) : "memory")
#define BAR_ARRIVE(id, cnt) asm volatile("bar.arrive %0, %1;" :: "r"(id), "r"(cnt) : "memory")

// Named-barrier map:
//   1              : G0 startup-only internal sync (s = 1, 2)
//   3              : G2 internal state-order sync (128)
//   4+k  (k=0..2)  : h1 ring slot k READY  (G0 arrive, G1 sync; 256)
//   7+k            : h1 ring slot k FREE   (G1 arrive, G0 sync; 256)
//   10+k           : gx ring slot k READY  (G1 arrive, G2 sync; 256)
//   13+k           : gx ring slot k FREE   (G2 arrive, G1 sync; 256)
// bar.arrive carries release semantics for the producer's smem stores
// (standard producer/consumer named-barrier pattern) — no drain syncs needed.

// ---------------------------------------------------------------------------
// Pipelined fused 2-layer GRU. Grid 128 x 384; CTA owns 4 batch rows.
// Three 4-warp groups (warp w -> SMSP w%4), depth-3 smem rings:
//   G0: h1[s] = GRU0(h1[s-1], x[s])  -> r_h1[s%3]
//   G1: gx[s] = Wih1 . r_h1[s%3]     -> r_gx[s%3]  (pair-reduced full values)
//   G2: h2[s] = GRU1(h2[s-1], gx[s]) -> global out
// Critical-path discipline: G0 waits ring-free at loop TOP (rendezvous that
// also guards its own next-step reads), stores then arrives immediately;
// G2 dots first, loads gx, releases the slot BEFORE its gate math.
// ---------------------------------------------------------------------------
__global__ void __launch_bounds__(384, 1) gru_pipe(
    const float* __restrict__ x,
    const float* __restrict__ W_ih0, const float* __restrict__ W_hh0,
    const float* __restrict__ b_ih0, const float* __restrict__ b_hh0,
    const float* __restrict__ W_ih1, const float* __restrict__ W_hh1,
    const float* __restrict__ b_ih1, const float* __restrict__ b_hh1,
    float* __restrict__ outp,        // (B,T,64)
    float* __restrict__ finalp)      // (B,64)
{
    __shared__ float r_h1[3][4][2][36];    // h1 ring  [slot][row][kgrp][32+pad]
    __shared__ float r_gx[3][4][200];      // gx ring  [slot][row][gate*64+j]; stride 200 -> bank offset 8/row
    __shared__ float p_h2[2][4][2][36];    // G2-private state (parity)
    __shared__ float sh_x[2][4][3];        // staged x[t]

    const int tx   = threadIdx.x;
    const int grp  = tx >> 7;            // 0,1,2
    const int lt   = tx & 127;
    const int half = lt & 1;
    const int j    = lt >> 1;            // 0..63
    const int kb   = half * 32;
    const int row4 = blockIdx.x * 4;

    // ---- init ----
    for (int i = tx; i < 3 * 4 * 2 * 36; i += 384)
        (&r_h1[0][0][0][0])[i] = 0.f;
    for (int i = tx; i < 2 * 4 * 2 * 36; i += 384)
        (&p_h2[0][0][0][0])[i] = 0.f;
    if (tx < 12)
        sh_x[0][tx / 3][tx % 3] =
            __ldg(&x[((size_t)(row4 + tx / 3) * Tsz) * 3 + tx % 3]);
    __syncthreads();

#define LOAD_W(Wsrc)                                                         \
    {                                                                        \
        const ull* __restrict__ Wll = reinterpret_cast<const ull*>(Wsrc);    \
        _Pragma("unroll")                                                    \
        for (int g3 = 0; g3 < 3; g3++) {                                     \
            const int g = j + g3 * 64;                                       \
            _Pragma("unroll")                                                \
            for (int kk = 0; kk < 16; kk++)                                  \
                w2[g3 * 16 + kk] = Wll[(g * 64 + kb) / 2 + kk];              \
        }                                                                    \
    }

#define DOT_ROW(hbase, r, pr, pz, pn)                                        \
    {                                                                        \
        const ulonglong2* __restrict__ hb =                                  \
            reinterpret_cast<const ulonglong2*>((hbase) + (r) * 72 + half * 36); \
        ull a0 = 0ull, a1 = 0ull, a2 = 0ull;                                 \
        _Pragma("unroll")                                                    \
        for (int i = 0; i < 8; i++) {                                        \
            const ulonglong2 h4 = hb[i];                                     \
            a0 = ffma2(h4.x, w2[2 * i],          a0);                        \
            a0 = ffma2(h4.y, w2[2 * i + 1],      a0);                        \
            a1 = ffma2(h4.x, w2[16 + 2 * i],     a1);                        \
            a1 = ffma2(h4.y, w2[16 + 2 * i + 1], a1);                        \
            a2 = ffma2(h4.x, w2[32 + 2 * i],     a2);                        \
            a2 = ffma2(h4.y, w2[32 + 2 * i + 1], a2);                        \
        }                                                                    \
        float l_, h_;                                                        \
        unpack2(a0, l_, h_); pr = l_ + h_;                                   \
        unpack2(a1, l_, h_); pz = l_ + h_;                                   \
        unpack2(a2, l_, h_); pn = l_ + h_;                                   \
    }

    // 6-shfl exchange: full sums for MY two rows (2*half, 2*half+1).
#define PAIR_REDUCE(s0, s1, s2, s3, fullA, fullB)                            \
    {                                                                        \
        const float sendA = half ? s0 : s2;                                  \
        const float sendB = half ? s1 : s3;                                  \
        const float mineA = half ? s2 : s0;                                  \
        const float mineB = half ? s3 : s1;                                  \
        fullA = mineA + __shfl_xor_sync(~0u, sendA, 1);                      \
        fullB = mineB + __shfl_xor_sync(~0u, sendB, 1);                      \
    }

    if (grp == 0) {
        // ================= G0: layer-0 engine =================
        ull w2[48];
        LOAD_W(W_hh0);
        float wi0[9];
#pragma unroll
        for (int g3 = 0; g3 < 3; g3++)
#pragma unroll
            for (int c = 0; c < 3; c++)
                wi0[g3 * 3 + c] = W_ih0[(j + g3 * 64) * 3 + c];
        const float bR  = b_ih0[j]       + b_hh0[j];
        const float bZ  = b_ih0[j + 64]  + b_hh0[j + 64];
        const float bXN = b_ih0[j + 128];
        const float bHN = b_hh0[j + 128];

        float hp[2] = {0.f, 0.f};            // rows 2*half, 2*half+1
        const int rA = 2 * half;

        int slot = 0, prev = 2;
        for (int s = 0; s < Tsz; s++) {
            const int par = s & 1;
            // top-of-loop rendezvous: ring-slot free + intra-G0 store/read order
            if (s >= 3)      BAR_SYNC(7 + slot, 256);
            else if (s >= 1) BAR_SYNC(1, 128);

            float xpre = 0.f;
            if (lt < 12 && s + 1 < Tsz)
                xpre = __ldg(&x[((size_t)(row4 + lt / 3) * Tsz + (s + 1)) * 3 + lt % 3]);

            float s0r, s0z, s0n, s1r, s1z, s1n, s2r, s2z, s2n, s3r, s3z, s3n;
            const float* hb0 = &r_h1[prev][0][0][0];
            DOT_ROW(hb0, 0, s0r, s0z, s0n);
            DOT_ROW(hb0, 1, s1r, s1z, s1n);
            DOT_ROW(hb0, 2, s2r, s2z, s2n);
            DOT_ROW(hb0, 3, s3r, s3z, s3n);
            float prA, prB, pzA, pzB, pnA, pnB;
            PAIR_REDUCE(s0r, s1r, s2r, s3r, prA, prB);
            PAIR_REDUCE(s0z, s1z, s2z, s3z, pzA, pzB);
            PAIR_REDUCE(s0n, s1n, s2n, s3n, pnA, pnB);

#pragma unroll
            for (int k = 0; k < 2; k++) {
                const int  rr = rA + k;
                const float pr = k ? prB : prA;
                const float pz = k ? pzB : pzA;
                const float pn = k ? pnB : pnA;
                const float x0 = sh_x[par][rr][0];
                const float x1 = sh_x[par][rr][1];
                const float x2 = sh_x[par][rr][2];
                const float ar  = pr + fmaf(x2, wi0[2], fmaf(x1, wi0[1], fmaf(x0, wi0[0], bR)));
                const float az  = pz + fmaf(x2, wi0[5], fmaf(x1, wi0[4], fmaf(x0, wi0[3], bZ)));
                const float xan =      fmaf(x2, wi0[8], fmaf(x1, wi0[7], fmaf(x0, wi0[6], bXN)));
                const float rg = fsigmoid(ar);
                const float zg = fsigmoid(az);
                const float nn = ftanh(fmaf(rg, pn + bHN, xan));
                const float hn = fmaf(zg, hp[k] - nn, nn);
                hp[k] = hn;
                r_h1[slot][rr][j >> 5][j & 31] = hn;
            }
            if (lt < 12 && s + 1 < Tsz)
                sh_x[par ^ 1][lt / 3][lt % 3] = xpre;

            BAR_ARRIVE(4 + slot, 256);    // h1[s] ready (release)
            prev = slot; slot = (slot == 2) ? 0 : slot + 1;
        }
    } else if (grp == 1) {
        // ================= G1: gx engine =================
        ull w2[48];
        LOAD_W(W_ih1);
        const float bR = b_ih1[j]       + b_hh1[j];
        const float bZ = b_ih1[j + 64]  + b_hh1[j + 64];
        const float bN = b_ih1[j + 128];
        const int rA = 2 * half;

        int slot = 0;
        for (int s = 0; s < Tsz; s++) {
            BAR_SYNC(4 + slot, 256);      // h1[s] ready

            float pr[4], pz[4], pn[4];
            const float* hb0 = &r_h1[slot][0][0][0];
#pragma unroll
            for (int r = 0; r < 4; r++)
                DOT_ROW(hb0, r, pr[r], pz[r], pn[r]);
            BAR_ARRIVE(7 + slot, 256);    // done reading h1 ring

            // pair-reduce: full gx for my two rows (G1 has slack for shfl)
            float prA, prB, pzA, pzB, pnA, pnB;
            PAIR_REDUCE(pr[0], pr[1], pr[2], pr[3], prA, prB);
            PAIR_REDUCE(pz[0], pz[1], pz[2], pz[3], pzA, pzB);
            PAIR_REDUCE(pn[0], pn[1], pn[2], pn[3], pnA, pnB);

            if (s >= 3) BAR_SYNC(13 + slot, 256); // gx slot free

            // 6 conflict-free scalar STS (row stride 200 -> +8 bank offset)
            r_gx[slot][rA][j]            = prA + bR;
            r_gx[slot][rA][64 + j]       = pzA + bZ;
            r_gx[slot][rA][128 + j]      = pnA + bN;
            r_gx[slot][rA + 1][j]        = prB + bR;
            r_gx[slot][rA + 1][64 + j]   = pzB + bZ;
            r_gx[slot][rA + 1][128 + j]  = pnB + bN;

            BAR_ARRIVE(10 + slot, 256);   // gx[s] ready (release)
            slot = (slot == 2) ? 0 : slot + 1;
        }
    } else {
        // ================= G2: layer-1 engine + output =================
        ull w2[48];
        LOAD_W(W_hh1);
        const float bHN = b_hh1[j + 128];
        float hp[2] = {0.f, 0.f};
        const int rA = 2 * half;

        int slot = 0;
        for (int s = 0; s < Tsz; s++) {
            const int par = s & 1;

            // recurrent dots FIRST (private state) — overlaps G1's gx write
            float s0r, s0z, s0n, s1r, s1z, s1n, s2r, s2z, s2n, s3r, s3z, s3n;
            const float* hb0 = &p_h2[par][0][0][0];
            DOT_ROW(hb0, 0, s0r, s0z, s0n);
            DOT_ROW(hb0, 1, s1r, s1z, s1n);
            DOT_ROW(hb0, 2, s2r, s2z, s2n);
            DOT_ROW(hb0, 3, s3r, s3z, s3n);
            float prA, prB, pzA, pzB, pnA, pnB;
            PAIR_REDUCE(s0r, s1r, s2r, s3r, prA, prB);
            PAIR_REDUCE(s0z, s1z, s2z, s3z, pzA, pzB);
            PAIR_REDUCE(s0n, s1n, s2n, s3n, pnA, pnB);

            BAR_SYNC(10 + slot, 256);     // gx[s] ready (late wait)

            // load ALL gx first, release the slot, then gate math
            const float grA = r_gx[slot][rA][j];
            const float gzA = r_gx[slot][rA][64 + j];
            const float gnA = r_gx[slot][rA][128 + j];
            const float grB = r_gx[slot][rA + 1][j];
            const float gzB = r_gx[slot][rA + 1][64 + j];
            const float gnB = r_gx[slot][rA + 1][128 + j];
            BAR_ARRIVE(13 + slot, 256);   // gx slot free (early release)

#pragma unroll
            for (int k = 0; k < 2; k++) {
                const int  rr = rA + k;
                const float pr = k ? prB : prA;
                const float pz = k ? pzB : pzA;
                const float pn = k ? pnB : pnA;
                const float gr = k ? grB : grA;
                const float gz = k ? gzB : gzA;
                const float gn = k ? gnB : gnA;
                const float rg = fsigmoid(gr + pr);
                const float zg = fsigmoid(gz + pz);
                const float nn = ftanh(fmaf(rg, pn + bHN, gn));
                const float hn = fmaf(zg, hp[k] - nn, nn);
                hp[k] = hn;
                p_h2[par ^ 1][rr][j >> 5][j & 31] = hn;
                outp[((size_t)(row4 + rr) * Tsz + s) * Hs + j] = hn;
                if (s == Tsz - 1)
                    finalp[(row4 + rr) * Hs + j] = hn;
            }
            BAR_SYNC(3, 128);             // order p_h2 writes before next dots
            slot = (slot == 2) ? 0 : slot + 1;
        }
    }
#undef LOAD_W
#undef DOT_ROW
#undef PAIR_REDUCE
}

// ---------------------------------------------------------------------------
extern "C" void kernel_launch(void* const* d_in, const int* in_sizes, int n_in,
                              void* d_out, int out_size)
{
    (void)in_sizes; (void)n_in; (void)out_size;
    const float* x     = (const float*)d_in[0];
    const float* W_ih0 = (const float*)d_in[1];
    const float* W_hh0 = (const float*)d_in[2];
    const float* b_ih0 = (const float*)d_in[3];
    const float* b_hh0 = (const float*)d_in[4];
    const float* W_ih1 = (const float*)d_in[5];
    const float* W_hh1 = (const float*)d_in[6];
    const float* b_ih1 = (const float*)d_in[7];
    const float* b_hh1 = (const float*)d_in[8];

    float* out    = (float*)d_out;
    float* finalh = out + (size_t)Bsz * Tsz * Hs;

    gru_pipe<<<128, 384>>>(x, W_ih0, W_hh0, b_ih0, b_hh0,
                           W_ih1, W_hh1, b_ih1, b_hh1, out, finalh);
}

// round 15
// speedup vs baseline: 1.0186x; 1.0186x over previous
#include <cuda_runtime.h>
#include <cstddef>

namespace {
constexpr int Bsz = 512, Tsz = 1024, Hs = 64;
}

using ull = unsigned long long;

__device__ __forceinline__ void unpack2(ull v, float& lo, float& hi) {
    asm("mov.b64 {%0,%1},%2;" : "=f"(lo), "=f"(hi) : "l"(v));
}
__device__ __forceinline__ ull ffma2(ull a, ull b, ull c) {
    ull d;
    asm("fma.rn.f32x2 %0,%1,%2,%3;" : "=l"(d) : "l"(a), "l"(b), "l"(c));
    return d;
}
__device__ __forceinline__ float fast_ex2(float x) {
    float r; asm("ex2.approx.f32 %0,%1;" : "=f"(r) : "f"(x)); return r;
}
__device__ __forceinline__ float fast_rcp(float x) {
    float r; asm("rcp.approx.f32 %0,%1;" : "=f"(r) : "f"(x)); return r;
}
__device__ __forceinline__ float fsigmoid(float x) {
    return fast_rcp(1.0f + fast_ex2(-1.44269504f * x));
}
__device__ __forceinline__ float ftanh(float x) {
    float ax = fabsf(x);
    float t  = fast_ex2(-2.88539008f * ax);          // exp(-2|x|)
    float y  = (1.0f - t) * fast_rcp(1.0f + t);
    return copysignf(y, x);
}

#define BAR_SYNC(id, cnt)   asm volatile("bar.sync %0, %1;"   :: "r"(id), "r"(cnt) : "memory")
#define BAR_ARRIVE(id, cnt) asm volatile("bar.arrive %0, %1;" :: "r"(id), "r"(cnt) : "memory")

// Named-barrier map (R13 skeleton):
//   1/2/3          : internal drains for G0/G1/G2 (128)
//   4+k  (k=0..2)  : h1 ring slot k READY  (G0 arrive, G1 sync; 256)
//   7+k            : h1 ring slot k FREE   (G1 arrive, G0 sync; 256)
//   10+k           : gx ring slot k READY  (G1 arrive, G2 sync; 256)
//   13+k           : gx ring slot k FREE   (G2 arrive, G1 sync; 256)

// ---------------------------------------------------------------------------
// Pipelined fused 2-layer GRU. Grid 128 x 384; CTA owns 4 batch rows.
// Three 4-warp groups (warp w -> SMSP w%4), depth-3 smem rings:
//   G0: h1[s] = GRU0(h1[s-1], x[s])  -> r_h1[s%3]   (ring IS G0's state)
//   G1: gx[s] = Wih1 . r_h1[s%3]     -> r_gx[s%3]   (pair-reduced, bank-clean)
//   G2: h2[s] = GRU1(h2[s-1], gx[s]) -> global out
// R13 scheduling (G0 late ring-free wait; drains kept) + G1 conflict-free
// scalar gx stores + G2 early gx-slot release.
// ---------------------------------------------------------------------------
__global__ void __launch_bounds__(384, 1) gru_pipe(
    const float* __restrict__ x,
    const float* __restrict__ W_ih0, const float* __restrict__ W_hh0,
    const float* __restrict__ b_ih0, const float* __restrict__ b_hh0,
    const float* __restrict__ W_ih1, const float* __restrict__ W_hh1,
    const float* __restrict__ b_ih1, const float* __restrict__ b_hh1,
    float* __restrict__ outp,        // (B,T,64)
    float* __restrict__ finalp)      // (B,64)
{
    __shared__ float r_h1[3][4][2][36];    // h1 ring  [slot][row][kgrp][32+pad]
    __shared__ float r_gx[3][4][200];      // gx ring  [slot][row][gate*64+j]; stride 200 -> bank rotate 8/row
    __shared__ float p_h2[2][4][2][36];    // G2-private state (parity)
    __shared__ float sh_x[2][4][3];        // staged x[t]

    const int tx   = threadIdx.x;
    const int grp  = tx >> 7;            // 0,1,2
    const int lt   = tx & 127;
    const int half = lt & 1;
    const int j    = lt >> 1;            // 0..63
    const int kb   = half * 32;
    const int row4 = blockIdx.x * 4;

    // ---- init ----
    for (int i = tx; i < 3 * 4 * 2 * 36; i += 384)
        (&r_h1[0][0][0][0])[i] = 0.f;
    for (int i = tx; i < 2 * 4 * 2 * 36; i += 384)
        (&p_h2[0][0][0][0])[i] = 0.f;
    if (tx < 12)
        sh_x[0][tx / 3][tx % 3] =
            __ldg(&x[((size_t)(row4 + tx / 3) * Tsz) * 3 + tx % 3]);
    __syncthreads();

#define LOAD_W(Wsrc)                                                         \
    {                                                                        \
        const ull* __restrict__ Wll = reinterpret_cast<const ull*>(Wsrc);    \
        _Pragma("unroll")                                                    \
        for (int g3 = 0; g3 < 3; g3++) {                                     \
            const int g = j + g3 * 64;                                       \
            _Pragma("unroll")                                                \
            for (int kk = 0; kk < 16; kk++)                                  \
                w2[g3 * 16 + kk] = Wll[(g * 64 + kb) / 2 + kk];              \
        }                                                                    \
    }

#define DOT_ROW(hbase, r, pr, pz, pn)                                        \
    {                                                                        \
        const ulonglong2* __restrict__ hb =                                  \
            reinterpret_cast<const ulonglong2*>((hbase) + (r) * 72 + half * 36); \
        ull a0 = 0ull, a1 = 0ull, a2 = 0ull;                                 \
        _Pragma("unroll")                                                    \
        for (int i = 0; i < 8; i++) {                                        \
            const ulonglong2 h4 = hb[i];                                     \
            a0 = ffma2(h4.x, w2[2 * i],          a0);                        \
            a0 = ffma2(h4.y, w2[2 * i + 1],      a0);                        \
            a1 = ffma2(h4.x, w2[16 + 2 * i],     a1);                        \
            a1 = ffma2(h4.y, w2[16 + 2 * i + 1], a1);                        \
            a2 = ffma2(h4.x, w2[32 + 2 * i],     a2);                        \
            a2 = ffma2(h4.y, w2[32 + 2 * i + 1], a2);                        \
        }                                                                    \
        float l_, h_;                                                        \
        unpack2(a0, l_, h_); pr = l_ + h_;                                   \
        unpack2(a1, l_, h_); pz = l_ + h_;                                   \
        unpack2(a2, l_, h_); pn = l_ + h_;                                   \
    }

    // 6-shfl exchange: full sums for MY two rows (2*half, 2*half+1).
#define PAIR_REDUCE(s0, s1, s2, s3, fullA, fullB)                            \
    {                                                                        \
        const float sendA = half ? s0 : s2;                                  \
        const float sendB = half ? s1 : s3;                                  \
        const float mineA = half ? s2 : s0;                                  \
        const float mineB = half ? s3 : s1;                                  \
        fullA = mineA + __shfl_xor_sync(~0u, sendA, 1);                      \
        fullB = mineB + __shfl_xor_sync(~0u, sendB, 1);                      \
    }

    if (grp == 0) {
        // ================= G0: layer-0 engine =================
        ull w2[48];
        LOAD_W(W_hh0);
        float wi0[9];
#pragma unroll
        for (int g3 = 0; g3 < 3; g3++)
#pragma unroll
            for (int c = 0; c < 3; c++)
                wi0[g3 * 3 + c] = W_ih0[(j + g3 * 64) * 3 + c];
        const float bR  = b_ih0[j]       + b_hh0[j];
        const float bZ  = b_ih0[j + 64]  + b_hh0[j + 64];
        const float bXN = b_ih0[j + 128];
        const float bHN = b_hh0[j + 128];

        float hp[2] = {0.f, 0.f};            // rows 2*half, 2*half+1
        const int rA = 2 * half;

        int slot = 0, prev = 2;              // slot = s%3, prev = (s-1)%3
        for (int s = 0; s < Tsz; s++) {
            const int par = s & 1;
            // prefetch x[s+1] early (latency under the dots)
            float xpre = 0.f;
            if (lt < 12 && s + 1 < Tsz)
                xpre = __ldg(&x[((size_t)(row4 + lt / 3) * Tsz + (s + 1)) * 3 + lt % 3]);

            float s0r, s0z, s0n, s1r, s1z, s1n, s2r, s2z, s2n, s3r, s3z, s3n;
            const float* hb0 = &r_h1[prev][0][0][0];
            DOT_ROW(hb0, 0, s0r, s0z, s0n);
            DOT_ROW(hb0, 1, s1r, s1z, s1n);
            DOT_ROW(hb0, 2, s2r, s2z, s2n);
            DOT_ROW(hb0, 3, s3r, s3z, s3n);
            float prA, prB, pzA, pzB, pnA, pnB;
            PAIR_REDUCE(s0r, s1r, s2r, s3r, prA, prB);
            PAIR_REDUCE(s0z, s1z, s2z, s3z, pzA, pzB);
            PAIR_REDUCE(s0n, s1n, s2n, s3n, pnA, pnB);

            float hn2[2];
#pragma unroll
            for (int k = 0; k < 2; k++) {
                const int  rr = rA + k;
                const float pr = k ? prB : prA;
                const float pz = k ? pzB : pzA;
                const float pn = k ? pnB : pnA;
                const float x0 = sh_x[par][rr][0];
                const float x1 = sh_x[par][rr][1];
                const float x2 = sh_x[par][rr][2];
                const float ar  = pr + fmaf(x2, wi0[2], fmaf(x1, wi0[1], fmaf(x0, wi0[0], bR)));
                const float az  = pz + fmaf(x2, wi0[5], fmaf(x1, wi0[4], fmaf(x0, wi0[3], bZ)));
                const float xan =      fmaf(x2, wi0[8], fmaf(x1, wi0[7], fmaf(x0, wi0[6], bXN)));
                const float rg = fsigmoid(ar);
                const float zg = fsigmoid(az);
                const float nn = ftanh(fmaf(rg, pn + bHN, xan));
                hn2[k] = fmaf(zg, hp[k] - nn, nn);
                hp[k]  = hn2[k];
            }

            if (s >= 3) BAR_SYNC(7 + slot, 256);   // slot free (late wait)
            r_h1[slot][rA][j >> 5][j & 31]     = hn2[0];
            r_h1[slot][rA + 1][j >> 5][j & 31] = hn2[1];
            if (lt < 12 && s + 1 < Tsz)
                sh_x[par ^ 1][lt / 3][lt % 3] = xpre;

            BAR_SYNC(1, 128);             // drain STS
            BAR_ARRIVE(4 + slot, 256);    // h1[s] ready
            prev = slot; slot = (slot == 2) ? 0 : slot + 1;
        }
    } else if (grp == 1) {
        // ================= G1: gx engine =================
        ull w2[48];
        LOAD_W(W_ih1);
        const float bR = b_ih1[j]       + b_hh1[j];
        const float bZ = b_ih1[j + 64]  + b_hh1[j + 64];
        const float bN = b_ih1[j + 128];
        const int rA = 2 * half;

        int slot = 0;
        for (int s = 0; s < Tsz; s++) {
            BAR_SYNC(4 + slot, 256);      // h1[s] ready

            float pr[4], pz[4], pn[4];
            const float* hb0 = &r_h1[slot][0][0][0];
#pragma unroll
            for (int r = 0; r < 4; r++)
                DOT_ROW(hb0, r, pr[r], pz[r], pn[r]);
            BAR_ARRIVE(7 + slot, 256);    // done reading h1 ring

            // pair-reduce: full gx for my two rows (G1 is the slack group)
            float prA, prB, pzA, pzB, pnA, pnB;
            PAIR_REDUCE(pr[0], pr[1], pr[2], pr[3], prA, prB);
            PAIR_REDUCE(pz[0], pz[1], pz[2], pz[3], pzA, pzB);
            PAIR_REDUCE(pn[0], pn[1], pn[2], pn[3], pnA, pnB);

            if (s >= 3) BAR_SYNC(13 + slot, 256); // gx slot free

            // 6 conflict-free scalar STS (row stride 200 -> bank rotate 8)
            r_gx[slot][rA][j]            = prA + bR;
            r_gx[slot][rA][64 + j]       = pzA + bZ;
            r_gx[slot][rA][128 + j]      = pnA + bN;
            r_gx[slot][rA + 1][j]        = prB + bR;
            r_gx[slot][rA + 1][64 + j]   = pzB + bZ;
            r_gx[slot][rA + 1][128 + j]  = pnB + bN;

            BAR_SYNC(2, 128);             // drain gx STS
            BAR_ARRIVE(10 + slot, 256);   // gx[s] ready
            slot = (slot == 2) ? 0 : slot + 1;
        }
    } else {
        // ================= G2: layer-1 engine + output =================
        ull w2[48];
        LOAD_W(W_hh1);
        const float bHN = b_hh1[j + 128];
        float hp[2] = {0.f, 0.f};
        const int rA = 2 * half;

        int slot = 0;
        for (int s = 0; s < Tsz; s++) {
            const int par = s & 1;

            // recurrent dots FIRST (private state) — overlaps G1's gx write
            float s0r, s0z, s0n, s1r, s1z, s1n, s2r, s2z, s2n, s3r, s3z, s3n;
            const float* hb0 = &p_h2[par][0][0][0];
            DOT_ROW(hb0, 0, s0r, s0z, s0n);
            DOT_ROW(hb0, 1, s1r, s1z, s1n);
            DOT_ROW(hb0, 2, s2r, s2z, s2n);
            DOT_ROW(hb0, 3, s3r, s3z, s3n);
            float prA, prB, pzA, pzB, pnA, pnB;
            PAIR_REDUCE(s0r, s1r, s2r, s3r, prA, prB);
            PAIR_REDUCE(s0z, s1z, s2z, s3z, pzA, pzB);
            PAIR_REDUCE(s0n, s1n, s2n, s3n, pnA, pnB);

            BAR_SYNC(10 + slot, 256);     // gx[s] ready (late wait)

            // load ALL gx first, release the slot, then gate math
            const float grA = r_gx[slot][rA][j];
            const float gzA = r_gx[slot][rA][64 + j];
            const float gnA = r_gx[slot][rA][128 + j];
            const float grB = r_gx[slot][rA + 1][j];
            const float gzB = r_gx[slot][rA + 1][64 + j];
            const float gnB = r_gx[slot][rA + 1][128 + j];
            BAR_ARRIVE(13 + slot, 256);   // gx slot free (early release)

#pragma unroll
            for (int k = 0; k < 2; k++) {
                const int  rr = rA + k;
                const float pr = k ? prB : prA;
                const float pz = k ? pzB : pzA;
                const float pn = k ? pnB : pnA;
                const float gr = k ? grB : grA;
                const float gz = k ? gzB : gzA;
                const float gn = k ? gnB : gnA;
                const float rg = fsigmoid(gr + pr);
                const float zg = fsigmoid(gz + pz);
                const float nn = ftanh(fmaf(rg, pn + bHN, gn));
                const float hn = fmaf(zg, hp[k] - nn, nn);
                hp[k] = hn;
                p_h2[par ^ 1][rr][j >> 5][j & 31] = hn;
                outp[((size_t)(row4 + rr) * Tsz + s) * Hs + j] = hn;
                if (s == Tsz - 1)
                    finalp[(row4 + rr) * Hs + j] = hn;
            }
            BAR_SYNC(3, 128);             // order p_h2 writes before next dots
            slot = (slot == 2) ? 0 : slot + 1;
        }
    }
#undef LOAD_W
#undef DOT_ROW
#undef PAIR_REDUCE
}

// ---------------------------------------------------------------------------
extern "C" void kernel_launch(void* const* d_in, const int* in_sizes, int n_in,
                              void* d_out, int out_size)
{
    (void)in_sizes; (void)n_in; (void)out_size;
    const float* x     = (const float*)d_in[0];
    const float* W_ih0 = (const float*)d_in[1];
    const float* W_hh0 = (const float*)d_in[2];
    const float* b_ih0 = (const float*)d_in[3];
    const float* b_hh0 = (const float*)d_in[4];
    const float* W_ih1 = (const float*)d_in[5];
    const float* W_hh1 = (const float*)d_in[6];
    const float* b_ih1 = (const float*)d_in[7];
    const float* b_hh1 = (const float*)d_in[8];

    float* out    = (float*)d_out;
    float* finalh = out + (size_t)Bsz * Tsz * Hs;

    gru_pipe<<<128, 384>>>(x, W_ih0, W_hh0, b_ih0, b_hh0,
                           W_ih1, W_hh1, b_ih1, b_hh1, out, finalh);
}